// round 16
// baseline (speedup 1.0000x reference)
#include <cuda_runtime.h>
#include <cuda_fp16.h>
#include <cuda_bf16.h>

// Problem constants
#define Bz 16
#define Nn 5000
#define Ff 64
#define Hh 32
#define Ee 160000
#define Aa 16
#define NE (Ee + Nn)          // 165000 edges incl self loops
#define NH (Nn * Hh)          // 160000 = K of policy GEMM
#define Jj 512                // policy hidden
#define SPLITS 295
#define KLEN 544              // 295*544 = 160480 >= 160000, multiple of 16

typedef unsigned long long ull;

// ----------------------------- scratch (no allocs allowed) ------------------
__device__ int   g_is64;
__device__ int   g_deg[Nn];
__device__ int   g_ptr[Nn + 1];
__device__ int   g_cursor[Nn];
__device__ float g_dinv[Nn];
__device__ int   g_csr_src[NE];                   // stores src*128 (uint2 units)
__device__ __align__(16) __half g_y1h[Bz * NH];   // fp16 [n][b][h]
__device__ __align__(16) __half g_y2h[Bz * NH];   // fp16 [n][b][h]
__device__ __align__(16) float g_flatT[NH * Bz];  // layer2 out [k=n*32+h][b]
__device__ __align__(16) float g_partial[SPLITS * Jj * Bz];
__device__ __align__(16) float g_opart[32 * 256]; // per-block output partials

// ----------------------------- helpers --------------------------------------
__device__ __forceinline__ ull ffma2(ull a, ull b, ull c) {
    ull d;
    asm("fma.rn.f32x2 %0, %1, %2, %3;" : "=l"(d) : "l"(a), "l"(b), "l"(c));
    return d;
}
__device__ __forceinline__ ull pack2(float x) {
    ull d;
    unsigned u = __float_as_uint(x);
    asm("mov.b64 %0, {%1, %1};" : "=l"(d) : "r"(u));
    return d;
}
__device__ __forceinline__ float lo32(ull a) { return __uint_as_float((unsigned)a); }
__device__ __forceinline__ float hi32(ull a) { return __uint_as_float((unsigned)(a >> 32)); }
__device__ __forceinline__ unsigned h2bits(float a, float b) {
    unsigned r;
    asm("{ .reg .b16 lo, hi;\n"
        "  cvt.rn.f16.f32 lo, %1;\n"
        "  cvt.rn.f16.f32 hi, %2;\n"
        "  mov.b32 %0, {lo, hi}; }" : "=r"(r) : "f"(a), "f"(b));
    return r;
}
__device__ __forceinline__ float4 u2f4(uint2 v) {
    __half2 h0 = *reinterpret_cast<__half2*>(&v.x);
    __half2 h1 = *reinterpret_cast<__half2*>(&v.y);
    float2 f0 = __half22float2(h0);
    float2 f1 = __half22float2(h1);
    return make_float4(f0.x, f0.y, f1.x, f1.y);
}
__device__ __forceinline__ int load_idx(const void* ei, long long pos) {
    if (g_is64) return (int)((const long long*)ei)[pos];
    return ((const int*)ei)[pos];
}

// ------------------- 1. init: zero deg + detect int32/int64 -----------------
__global__ void k_init(const void* ei) {
    int tid = threadIdx.x;
    if (blockIdx.x < 20) {
        int i = blockIdx.x * 256 + tid;
        if (i < Nn) g_deg[i] = 0;
        return;
    }
    const unsigned* w = (const unsigned*)ei;
    unsigned o = 0;
    for (int i = tid; i < 2048; i += 256) o |= w[2 * i + 1]; // high words if i64
    __shared__ unsigned red[256];
    red[tid] = o;
    __syncthreads();
    for (int s = 128; s > 0; s >>= 1) {
        if (tid < s) red[tid] |= red[tid + s];
        __syncthreads();
    }
    if (tid == 0) g_is64 = (red[0] == 0u) ? 1 : 0;
}

// ------------------- 2. degree histogram (smem-privatized) -------------------
#define DEG_BLOCKS 8
#define DEG_EPB ((NE + DEG_BLOCKS - 1) / DEG_BLOCKS)   // 20625
__global__ void __launch_bounds__(1024) k_degree(const void* ei) {
    __shared__ int hist[Nn];            // 20 KB
    int tid = threadIdx.x;
    for (int i = tid; i < Nn; i += 1024) hist[i] = 0;
    __syncthreads();
    int s0 = blockIdx.x * DEG_EPB;
    int s1 = s0 + DEG_EPB;
    if (s1 > NE) s1 = NE;
#pragma unroll 4
    for (int e = s0 + tid; e < s1; e += 1024) {
        int d = (e < Ee) ? load_idx(ei, (long long)Ee + e) : (e - Ee);
        atomicAdd(&hist[d], 1);
    }
    __syncthreads();
    for (int i = tid; i < Nn; i += 1024) {
        int c = hist[i];
        if (c) atomicAdd(&g_deg[i], c);
    }
}

// ------------------- 3. scan: ptr, cursor, dinv (warp-shuffle) --------------
__global__ void __launch_bounds__(1024) k_scan() {
    __shared__ int warpsum[32];
    int t = threadIdx.x;
    int lane = t & 31, wid = t >> 5;
    int base = t * 5;
    int v[5];
    int s = 0;
#pragma unroll
    for (int i = 0; i < 5; i++) {
        int n = base + i;
        int d = (n < Nn) ? g_deg[n] : 0;
        v[i] = s;
        s += d;
        if (n < Nn) g_dinv[n] = rsqrtf((float)d);   // deg >= 1 (self loop)
    }
    int x = s;
#pragma unroll
    for (int o = 1; o < 32; o <<= 1) {
        int y = __shfl_up_sync(0xffffffffu, x, o);
        if (lane >= o) x += y;
    }
    if (lane == 31) warpsum[wid] = x;
    __syncthreads();
    if (wid == 0) {
        int y = warpsum[lane];
#pragma unroll
        for (int o = 1; o < 32; o <<= 1) {
            int z = __shfl_up_sync(0xffffffffu, y, o);
            if (lane >= o) y += z;
        }
        warpsum[lane] = y;
    }
    __syncthreads();
    int excl = x - s + ((wid > 0) ? warpsum[wid - 1] : 0);
#pragma unroll
    for (int i = 0; i < 5; i++) {
        int n = base + i;
        if (n < Nn) { g_ptr[n] = excl + v[i]; g_cursor[n] = excl + v[i]; }
    }
    if (t == 0) g_ptr[Nn] = NE;
}

// ------------------- 4a. bucket edges ----------------------------------------
#define BUCKET_BLOCKS ((NE + 255) / 256)   // 645
__global__ void k_bucket(const void* ei) {
    int idx = blockIdx.x * 256 + threadIdx.x;
    if (idx >= NE) return;
    int d, s;
    if (idx < Ee) {
        d = load_idx(ei, (long long)Ee + idx);
        s = load_idx(ei, idx);
    } else {
        d = s = idx - Ee;
    }
    int pos = atomicAdd(&g_cursor[d], 1);
    g_csr_src[pos] = s * 128;  // offset of node's 1KB block in uint2 units
}

// ------------------- 4b. y1 = dinv*(X@W1) in fp16 ---------------------------
#define XW1_BLOCKS (Bz * Nn / 128)         // 625, 128 rows/block
__global__ void __launch_bounds__(256) k_xw1(const float* __restrict__ X,
                                             const float* __restrict__ W1) {
    // 128 rows/block; thread = (g=h-slice of 8 [0..3], rg [0..63]); 2 rows each
    __shared__ __align__(16) ull sWp[Ff * 16];     // W1 as h-pairs  8KB
    __shared__ float sX[128 * 65];                 // [row][f] pad 65  33.3KB
    int tid = threadIdx.x;
    int rbase = blockIdx.x * 128;
    {
        const ull* w2 = (const ull*)W1;
        for (int i = tid; i < Ff * 16; i += 256) sWp[i] = w2[i];
        for (int i = tid; i < 128 * 64; i += 256) {
            int row = i >> 6, f = i & 63;
            sX[row * 65 + f] = X[(size_t)rbase * Ff + i];
        }
    }
    __syncthreads();
    int g = tid >> 6, rg = tid & 63;     // g = 0..3 (valid h-slices)
    ull acc[2][4];
#pragma unroll
    for (int j = 0; j < 2; j++)
#pragma unroll
        for (int p = 0; p < 4; p++) acc[j][p] = 0ull;
    const float* xr = &sX[rg * 65];
    const ulonglong2* wr = (const ulonglong2*)&sWp[g * 4];
#pragma unroll 16
    for (int f = 0; f < Ff; f++) {
        ulonglong2 wA = wr[f * 8];          // pairs g*4, g*4+1
        ulonglong2 wB = wr[f * 8 + 1];      // pairs g*4+2, g*4+3
#pragma unroll
        for (int j = 0; j < 2; j++) {
            ull xx = pack2(xr[j * 64 * 65 + f]);
            acc[j][0] = ffma2(xx, wA.x, acc[j][0]);
            acc[j][1] = ffma2(xx, wA.y, acc[j][1]);
            acc[j][2] = ffma2(xx, wB.x, acc[j][2]);
            acc[j][3] = ffma2(xx, wB.y, acc[j][3]);
        }
    }
#pragma unroll
    for (int j = 0; j < 2; j++) {
        int r = rbase + rg + 64 * j;        // r = b*5000 + n
        int bb = r / Nn;
        int n = r - bb * Nn;
        float di = g_dinv[n];
        uint4 pack;
        pack.x = h2bits(di * lo32(acc[j][0]), di * hi32(acc[j][0]));
        pack.y = h2bits(di * lo32(acc[j][1]), di * hi32(acc[j][1]));
        pack.z = h2bits(di * lo32(acc[j][2]), di * hi32(acc[j][2]));
        pack.w = h2bits(di * lo32(acc[j][3]), di * hi32(acc[j][3]));
        // layout [n][b][h]: uint4 index = n*64 + b*4 + g
        ((uint4*)g_y1h)[(size_t)n * 64 + bb * 4 + g] = pack;
    }
}

// ------------------- 5. layer1 aggregate + relu + @W2 fused ------------------
// Block = 4 dst nodes. Warp = (dst, 4 batches); lane = (batch, h-quad).
// y layout [n][b][h] -> warp reads contiguous 256B per edge.
__global__ void __launch_bounds__(512) k_agg1(const float* __restrict__ W2,
                                              const float* __restrict__ b1) {
    __shared__ float sW2[Hh * Hh];     // 4KB
    int tid = threadIdx.x;
    sW2[tid] = W2[tid];
    sW2[tid + 512] = W2[tid + 512];
    int w = tid >> 5, l = tid & 31;
    int dd = w >> 2;                    // 0..3
    int d = blockIdx.x * 4 + dd;
    int b = ((w & 3) << 2) + (l >> 3);  // batch 0..15
    int hq = l & 7;                     // h-quad 0..7 (halves 4hq..4hq+3)
    __syncthreads();
    int start = __ldg(&g_ptr[d]), end = __ldg(&g_ptr[d + 1]);
    const uint2* yb = (const uint2*)g_y1h + b * 8 + hq;  // lane-constant
    float4 a0 = {0,0,0,0}, a1 = {0,0,0,0}, a2 = {0,0,0,0}, a3 = {0,0,0,0};
    int e = start;
    for (; e + 3 < end; e += 4) {
        int o0 = __ldg(&g_csr_src[e]);
        int o1 = __ldg(&g_csr_src[e + 1]);
        int o2 = __ldg(&g_csr_src[e + 2]);
        int o3 = __ldg(&g_csr_src[e + 3]);
        float4 v0 = u2f4(__ldg(yb + o0));
        float4 v1 = u2f4(__ldg(yb + o1));
        float4 v2 = u2f4(__ldg(yb + o2));
        float4 v3 = u2f4(__ldg(yb + o3));
        a0.x += v0.x; a0.y += v0.y; a0.z += v0.z; a0.w += v0.w;
        a1.x += v1.x; a1.y += v1.y; a1.z += v1.z; a1.w += v1.w;
        a2.x += v2.x; a2.y += v2.y; a2.z += v2.z; a2.w += v2.w;
        a3.x += v3.x; a3.y += v3.y; a3.z += v3.z; a3.w += v3.w;
    }
    for (; e < end; e++) {
        float4 v = u2f4(__ldg(yb + __ldg(&g_csr_src[e])));
        a0.x += v.x; a0.y += v.y; a0.z += v.z; a0.w += v.w;
    }
    float4 s4;
    s4.x = (a0.x + a1.x) + (a2.x + a3.x);
    s4.y = (a0.y + a1.y) + (a2.y + a3.y);
    s4.z = (a0.z + a1.z) + (a2.z + a3.z);
    s4.w = (a0.w + a1.w) + (a2.w + a3.w);
    float di = g_dinv[d];
    float4 bias = __ldg(&((const float4*)b1)[hq]);
    float4 hv;
    hv.x = fmaxf(di * s4.x + bias.x, 0.f);
    hv.y = fmaxf(di * s4.y + bias.y, 0.f);
    hv.z = fmaxf(di * s4.z + bias.z, 0.f);
    hv.w = fmaxf(di * s4.w + bias.w, 0.f);
    // W2 multiply: out[h] = sum_h' hv[h'] * W2[h'][h], h' via 8-lane group shfl
    float4 out = {0,0,0,0};
    int srcbase = l & 24;               // start lane of my (dst,batch) group
#pragma unroll
    for (int q = 0; q < 8; q++) {
        float vx = __shfl_sync(0xffffffffu, hv.x, srcbase + q);  // h'=4q
        float vy = __shfl_sync(0xffffffffu, hv.y, srcbase + q);  // h'=4q+1
        float vz = __shfl_sync(0xffffffffu, hv.z, srcbase + q);  // h'=4q+2
        float vw = __shfl_sync(0xffffffffu, hv.w, srcbase + q);  // h'=4q+3
        float4 w0 = ((const float4*)&sW2[(4 * q) * Hh])[hq];
        float4 w1 = ((const float4*)&sW2[(4 * q + 1) * Hh])[hq];
        float4 w2v = ((const float4*)&sW2[(4 * q + 2) * Hh])[hq];
        float4 w3 = ((const float4*)&sW2[(4 * q + 3) * Hh])[hq];
        out.x += vx * w0.x + vy * w1.x + vz * w2v.x + vw * w3.x;
        out.y += vx * w0.y + vy * w1.y + vz * w2v.y + vw * w3.y;
        out.z += vx * w0.z + vy * w1.z + vz * w2v.z + vw * w3.z;
        out.w += vx * w0.w + vy * w1.w + vz * w2v.w + vw * w3.w;
    }
    uint2 ob;
    ob.x = h2bits(di * out.x, di * out.y);
    ob.y = h2bits(di * out.z, di * out.w);
    // layout [n][b][h]: uint2 index = d*128 + b*8 + hq
    ((uint2*)g_y2h)[(size_t)d * 128 + b * 8 + hq] = ob;
}

// ------------------- 6. layer2 aggregate + relu -> flatT (fp32) -------------
__global__ void __launch_bounds__(512) k_agg2(const float* __restrict__ b2) {
    __shared__ float sT[4][Hh][17];
    int tid = threadIdx.x;
    int w = tid >> 5, l = tid & 31;
    int dd = w >> 2;
    int d = blockIdx.x * 4 + dd;
    int b = ((w & 3) << 2) + (l >> 3);
    int hq = l & 7;
    int start = __ldg(&g_ptr[d]), end = __ldg(&g_ptr[d + 1]);
    const uint2* yb = (const uint2*)g_y2h + b * 8 + hq;
    float4 a0 = {0,0,0,0}, a1 = {0,0,0,0}, a2 = {0,0,0,0}, a3 = {0,0,0,0};
    int e = start;
    for (; e + 3 < end; e += 4) {
        int o0 = __ldg(&g_csr_src[e]);
        int o1 = __ldg(&g_csr_src[e + 1]);
        int o2 = __ldg(&g_csr_src[e + 2]);
        int o3 = __ldg(&g_csr_src[e + 3]);
        float4 v0 = u2f4(__ldg(yb + o0));
        float4 v1 = u2f4(__ldg(yb + o1));
        float4 v2 = u2f4(__ldg(yb + o2));
        float4 v3 = u2f4(__ldg(yb + o3));
        a0.x += v0.x; a0.y += v0.y; a0.z += v0.z; a0.w += v0.w;
        a1.x += v1.x; a1.y += v1.y; a1.z += v1.z; a1.w += v1.w;
        a2.x += v2.x; a2.y += v2.y; a2.z += v2.z; a2.w += v2.w;
        a3.x += v3.x; a3.y += v3.y; a3.z += v3.z; a3.w += v3.w;
    }
    for (; e < end; e++) {
        float4 v = u2f4(__ldg(yb + __ldg(&g_csr_src[e])));
        a0.x += v.x; a0.y += v.y; a0.z += v.z; a0.w += v.w;
    }
    float di = g_dinv[d];
    float4 bias = __ldg(&((const float4*)b2)[hq]);
    sT[dd][4 * hq][b]     = fmaxf(di * ((a0.x + a1.x) + (a2.x + a3.x)) + bias.x, 0.f);
    sT[dd][4 * hq + 1][b] = fmaxf(di * ((a0.y + a1.y) + (a2.y + a3.y)) + bias.y, 0.f);
    sT[dd][4 * hq + 2][b] = fmaxf(di * ((a0.z + a1.z) + (a2.z + a3.z)) + bias.z, 0.f);
    sT[dd][4 * hq + 3][b] = fmaxf(di * ((a0.w + a1.w) + (a2.w + a3.w)) + bias.w, 0.f);
    __syncthreads();
    // write 2048 floats: flatT[(blockIdx*4+ddd)*512 + h*16 + b]
    size_t outbase = (size_t)blockIdx.x * 2048;
#pragma unroll
    for (int i = 0; i < 4; i++) {
        int idx = i * 512 + tid;
        int ddd = idx >> 9, j = idx & 511;
        g_flatT[outbase + idx] = sT[ddd][j >> 4][j & 15];
    }
}

// ------------------- 7. big GEMM: partial[split] = flatT^T chunk @ Wp1 -------
// 2 CTAs/SM; 16-row register double buffer -> 1KB/warp outstanding (full BW).
#define GEMM_COMPUTE16(BUF, KBASE)                                           \
    {                                                                        \
        _Pragma("unroll")                                                    \
        for (int i = 0; i < 16; i++) {                                       \
            ull wa = pack2(BUF[i].x);                                        \
            ull wb = pack2(BUF[i].y);                                        \
            const ulonglong2* f2 = &sF[((KBASE) + i) * 4];                   \
            _Pragma("unroll")                                                \
            for (int q = 0; q < 4; q++) {                                    \
                ulonglong2 fv = f2[q];                                       \
                acc0[2 * q]     = ffma2(fv.x, wa, acc0[2 * q]);              \
                acc0[2 * q + 1] = ffma2(fv.y, wa, acc0[2 * q + 1]);          \
                acc1[2 * q]     = ffma2(fv.x, wb, acc1[2 * q]);              \
                acc1[2 * q + 1] = ffma2(fv.y, wb, acc1[2 * q + 1]);          \
            }                                                                \
        }                                                                    \
    }

__global__ void __launch_bounds__(256, 2) k_gemm1(const float* __restrict__ Wp1) {
    __shared__ __align__(16) ulonglong2 sF[KLEN * 4];  // 34816 B
    int t = threadIdx.x, sp = blockIdx.x;
    int ks = sp * KLEN;
    int klen = NH - ks;
    if (klen > KLEN) klen = KLEN;          // klen in {544, 64}
    const ulonglong2* fp = (const ulonglong2*)(g_flatT + (size_t)ks * 16);
    for (int i = t; i < klen * 4; i += 256) sF[i] = __ldg(&fp[i]);
    __syncthreads();

    const float2* wp = (const float2*)Wp1 + (size_t)ks * 256 + t;
    ull acc0[8], acc1[8];
#pragma unroll
    for (int p = 0; p < 8; p++) { acc0[p] = 0ull; acc1[p] = 0ull; }

    int nb = klen >> 4;                    // 16-row chunks: 34 or 4 (even)
    float2 A[16], B[16];
#pragma unroll
    for (int i = 0; i < 16; i++) A[i] = __ldg(wp + i * 256);
    for (int bi = 0; bi < nb; bi += 2) {
        const float2* wq = wp + (size_t)(bi + 1) * 4096;
#pragma unroll
        for (int i = 0; i < 16; i++) B[i] = __ldg(wq + i * 256);
        GEMM_COMPUTE16(A, bi * 16)
        if (bi + 2 < nb) {
            const float2* wr2 = wp + (size_t)(bi + 2) * 4096;
#pragma unroll
            for (int i = 0; i < 16; i++) A[i] = __ldg(wr2 + i * 256);
        }
        GEMM_COMPUTE16(B, (bi + 1) * 16)
    }
    // store partials: layout [sp][j][b] with j0 = 2t
    ull* po = (ull*)g_partial;
    size_t base = (size_t)sp * 4096 + (size_t)(2 * t) * 8;
#pragma unroll
    for (int p = 0; p < 8; p++) {
        po[base + p] = acc0[p];
        po[base + 8 + p] = acc1[p];
    }
}

// ------------------- 8. reduce partials + bias + relu + out-partial ----------
__global__ void __launch_bounds__(256) k_reduce(const float* __restrict__ bp1,
                                                const float* __restrict__ Wp2) {
    __shared__ float sh[256];
    int tid = threadIdx.x;
    int idx = blockIdx.x * 256 + tid;           // [j][b]
    float s = 0.f;
#pragma unroll 8
    for (int sp = 0; sp < SPLITS; sp++) s += g_partial[(size_t)sp * 8192 + idx];
    sh[tid] = fmaxf(s + __ldg(&bp1[idx >> 4]), 0.f);
    __syncthreads();
    // out partial: thread = (b = tid>>4, a = tid&15)
    int b = tid >> 4, a = tid & 15;
    int jbase = blockIdx.x * 16;
    float acc = 0.f;
#pragma unroll
    for (int jl = 0; jl < 16; jl++)
        acc += sh[jl * 16 + b] * __ldg(&Wp2[(jbase + jl) * 16 + a]);
    g_opart[blockIdx.x * 256 + tid] = acc;
}

// ------------------- 9. final: sum 32 out-partials + bias -------------------
__global__ void __launch_bounds__(256) k_outB(const float* __restrict__ bp2,
                                              float* __restrict__ out) {
    int tid = threadIdx.x;
    float acc = 0.f;
#pragma unroll
    for (int k = 0; k < 32; k++) acc += g_opart[k * 256 + tid];
    out[tid] = acc + __ldg(&bp2[tid & 15]);
}

// ----------------------------- launcher -------------------------------------
extern "C" void kernel_launch(void* const* d_in, const int* in_sizes, int n_in,
                              void* d_out, int out_size) {
    const float* features = (const float*)d_in[0];
    const void*  edge_ix  = d_in[1];
    const float* W1  = (const float*)d_in[2];
    const float* b1  = (const float*)d_in[3];
    const float* W2  = (const float*)d_in[4];
    const float* b2  = (const float*)d_in[5];
    const float* Wp1 = (const float*)d_in[6];
    const float* bp1 = (const float*)d_in[7];
    const float* Wp2 = (const float*)d_in[8];
    const float* bp2 = (const float*)d_in[9];
    float* out = (float*)d_out;

    k_init<<<21, 256>>>(edge_ix);
    k_degree<<<DEG_BLOCKS, 1024>>>(edge_ix);
    k_scan<<<1, 1024>>>();
    k_bucket<<<BUCKET_BLOCKS, 256>>>(edge_ix);
    k_xw1<<<XW1_BLOCKS, 256>>>(features, W1);
    k_agg1<<<Nn / 4, 512>>>(W2, b1);
    k_agg2<<<Nn / 4, 512>>>(b2);
    k_gemm1<<<SPLITS, 256>>>(Wp1);
    k_reduce<<<Jj * Bz / 256, 256>>>(bp1, Wp2);
    k_outB<<<1, 256>>>(bp2, out);
}

// round 17
// speedup vs baseline: 1.0567x; 1.0567x over previous
#include <cuda_runtime.h>
#include <cuda_fp16.h>
#include <cuda_bf16.h>

// Problem constants
#define Bz 16
#define Nn 5000
#define Ff 64
#define Hh 32
#define Ee 160000
#define Aa 16
#define NE (Ee + Nn)          // 165000 edges incl self loops
#define NH (Nn * Hh)          // 160000 = K of policy GEMM
#define Jj 512                // policy hidden
#define SPLITS 295
#define KLEN 544              // 295*544 = 160480 >= 160000, multiple of 16

typedef unsigned long long ull;

// ----------------------------- scratch (no allocs allowed) ------------------
__device__ int   g_is64;
__device__ int   g_deg[Nn];
__device__ int   g_ptr[Nn + 1];
__device__ int   g_cursor[Nn];
__device__ float g_dinv[Nn];
__device__ int   g_csr_src[NE];                   // stores src*64 (uint4 units)
__device__ __align__(16) __half g_y1h[Bz * NH];   // fp16 [n][b][h]
__device__ __align__(16) __half g_y2h[Bz * NH];   // fp16 [n][b][h]
__device__ __align__(16) float g_flatT[NH * Bz];  // layer2 out [k=n*32+h][b]
__device__ __align__(16) float g_partial[SPLITS * Jj * Bz];
__device__ __align__(16) float g_opart[32 * 256]; // per-block output partials

// ----------------------------- helpers --------------------------------------
__device__ __forceinline__ ull ffma2(ull a, ull b, ull c) {
    ull d;
    asm("fma.rn.f32x2 %0, %1, %2, %3;" : "=l"(d) : "l"(a), "l"(b), "l"(c));
    return d;
}
__device__ __forceinline__ ull pack2(float x) {
    ull d;
    unsigned u = __float_as_uint(x);
    asm("mov.b64 %0, {%1, %1};" : "=l"(d) : "r"(u));
    return d;
}
__device__ __forceinline__ float lo32(ull a) { return __uint_as_float((unsigned)a); }
__device__ __forceinline__ float hi32(ull a) { return __uint_as_float((unsigned)(a >> 32)); }
__device__ __forceinline__ unsigned h2bits(float a, float b) {
    unsigned r;
    asm("{ .reg .b16 lo, hi;\n"
        "  cvt.rn.f16.f32 lo, %1;\n"
        "  cvt.rn.f16.f32 hi, %2;\n"
        "  mov.b32 %0, {lo, hi}; }" : "=r"(r) : "f"(a), "f"(b));
    return r;
}
__device__ __forceinline__ float2 h2f2(unsigned bits) {
    __half2 h = *reinterpret_cast<__half2*>(&bits);
    return __half22float2(h);
}
__device__ __forceinline__ int load_idx(const void* ei, long long pos) {
    if (g_is64) return (int)((const long long*)ei)[pos];
    return ((const int*)ei)[pos];
}

// ------------------- 1. init: zero deg + detect int32/int64 -----------------
__global__ void k_init(const void* ei) {
    int tid = threadIdx.x;
    if (blockIdx.x < 20) {
        int i = blockIdx.x * 256 + tid;
        if (i < Nn) g_deg[i] = 0;
        return;
    }
    const unsigned* w = (const unsigned*)ei;
    unsigned o = 0;
    for (int i = tid; i < 2048; i += 256) o |= w[2 * i + 1]; // high words if i64
    __shared__ unsigned red[256];
    red[tid] = o;
    __syncthreads();
    for (int s = 128; s > 0; s >>= 1) {
        if (tid < s) red[tid] |= red[tid + s];
        __syncthreads();
    }
    if (tid == 0) g_is64 = (red[0] == 0u) ? 1 : 0;
}

// ------------------- 2. degree histogram (smem-privatized) -------------------
#define DEG_BLOCKS 8
#define DEG_EPB ((NE + DEG_BLOCKS - 1) / DEG_BLOCKS)   // 20625
__global__ void __launch_bounds__(1024) k_degree(const void* ei) {
    __shared__ int hist[Nn];            // 20 KB
    int tid = threadIdx.x;
    for (int i = tid; i < Nn; i += 1024) hist[i] = 0;
    __syncthreads();
    int s0 = blockIdx.x * DEG_EPB;
    int s1 = s0 + DEG_EPB;
    if (s1 > NE) s1 = NE;
#pragma unroll 4
    for (int e = s0 + tid; e < s1; e += 1024) {
        int d = (e < Ee) ? load_idx(ei, (long long)Ee + e) : (e - Ee);
        atomicAdd(&hist[d], 1);
    }
    __syncthreads();
    for (int i = tid; i < Nn; i += 1024) {
        int c = hist[i];
        if (c) atomicAdd(&g_deg[i], c);
    }
}

// ------------------- 3. scan: ptr, cursor, dinv (warp-shuffle) --------------
__global__ void __launch_bounds__(1024) k_scan() {
    __shared__ int warpsum[32];
    int t = threadIdx.x;
    int lane = t & 31, wid = t >> 5;
    int base = t * 5;
    int v[5];
    int s = 0;
#pragma unroll
    for (int i = 0; i < 5; i++) {
        int n = base + i;
        int d = (n < Nn) ? g_deg[n] : 0;
        v[i] = s;
        s += d;
        if (n < Nn) g_dinv[n] = rsqrtf((float)d);   // deg >= 1 (self loop)
    }
    int x = s;
#pragma unroll
    for (int o = 1; o < 32; o <<= 1) {
        int y = __shfl_up_sync(0xffffffffu, x, o);
        if (lane >= o) x += y;
    }
    if (lane == 31) warpsum[wid] = x;
    __syncthreads();
    if (wid == 0) {
        int y = warpsum[lane];
#pragma unroll
        for (int o = 1; o < 32; o <<= 1) {
            int z = __shfl_up_sync(0xffffffffu, y, o);
            if (lane >= o) y += z;
        }
        warpsum[lane] = y;
    }
    __syncthreads();
    int excl = x - s + ((wid > 0) ? warpsum[wid - 1] : 0);
#pragma unroll
    for (int i = 0; i < 5; i++) {
        int n = base + i;
        if (n < Nn) { g_ptr[n] = excl + v[i]; g_cursor[n] = excl + v[i]; }
    }
    if (t == 0) g_ptr[Nn] = NE;
}

// ------------------- 4a. bucket edges ----------------------------------------
#define BUCKET_BLOCKS ((NE + 255) / 256)   // 645
__global__ void k_bucket(const void* ei) {
    int idx = blockIdx.x * 256 + threadIdx.x;
    if (idx >= NE) return;
    int d, s;
    if (idx < Ee) {
        d = load_idx(ei, (long long)Ee + idx);
        s = load_idx(ei, idx);
    } else {
        d = s = idx - Ee;
    }
    int pos = atomicAdd(&g_cursor[d], 1);
    g_csr_src[pos] = s * 64;   // offset of node's 1KB block in uint4 units
}

// ------------------- 4b. y1 = dinv*(X@W1) in fp16 ---------------------------
#define XW1_BLOCKS (Bz * Nn / 128)         // 625, 128 rows/block
__global__ void __launch_bounds__(256) k_xw1(const float* __restrict__ X,
                                             const float* __restrict__ W1) {
    // 128 rows/block; thread = (g=h-slice of 8 [0..3], rg [0..63]); 2 rows each
    __shared__ __align__(16) ull sWp[Ff * 16];     // W1 as h-pairs  8KB
    __shared__ float sX[128 * 65];                 // [row][f] pad 65  33.3KB
    int tid = threadIdx.x;
    int rbase = blockIdx.x * 128;
    {
        const ull* w2 = (const ull*)W1;
        for (int i = tid; i < Ff * 16; i += 256) sWp[i] = w2[i];
        for (int i = tid; i < 128 * 64; i += 256) {
            int row = i >> 6, f = i & 63;
            sX[row * 65 + f] = X[(size_t)rbase * Ff + i];
        }
    }
    __syncthreads();
    int g = tid >> 6, rg = tid & 63;     // g = 0..3 (valid h-slices)
    ull acc[2][4];
#pragma unroll
    for (int j = 0; j < 2; j++)
#pragma unroll
        for (int p = 0; p < 4; p++) acc[j][p] = 0ull;
    const float* xr = &sX[rg * 65];
    const ulonglong2* wr = (const ulonglong2*)&sWp[g * 4];
#pragma unroll 16
    for (int f = 0; f < Ff; f++) {
        ulonglong2 wA = wr[f * 8];          // pairs g*4, g*4+1
        ulonglong2 wB = wr[f * 8 + 1];      // pairs g*4+2, g*4+3
#pragma unroll
        for (int j = 0; j < 2; j++) {
            ull xx = pack2(xr[j * 64 * 65 + f]);
            acc[j][0] = ffma2(xx, wA.x, acc[j][0]);
            acc[j][1] = ffma2(xx, wA.y, acc[j][1]);
            acc[j][2] = ffma2(xx, wB.x, acc[j][2]);
            acc[j][3] = ffma2(xx, wB.y, acc[j][3]);
        }
    }
#pragma unroll
    for (int j = 0; j < 2; j++) {
        int r = rbase + rg + 64 * j;        // r = b*5000 + n
        int bb = r / Nn;
        int n = r - bb * Nn;
        float di = g_dinv[n];
        uint4 pack;
        pack.x = h2bits(di * lo32(acc[j][0]), di * hi32(acc[j][0]));
        pack.y = h2bits(di * lo32(acc[j][1]), di * hi32(acc[j][1]));
        pack.z = h2bits(di * lo32(acc[j][2]), di * hi32(acc[j][2]));
        pack.w = h2bits(di * lo32(acc[j][3]), di * hi32(acc[j][3]));
        // layout [n][b][h]: uint4 index = n*64 + b*4 + g
        ((uint4*)g_y1h)[(size_t)n * 64 + bb * 4 + g] = pack;
    }
}

// ------------------- 5. layer1 aggregate + relu + @W2 fused ------------------
// Block = 8 dst nodes. Warp = (dst, 8 batches); lane = (batch, h-oct).
// Lane loads uint4 (8 halves). Warp reads contiguous 512B per edge.
__global__ void __launch_bounds__(512) k_agg1(const float* __restrict__ W2,
                                              const float* __restrict__ b1) {
    __shared__ float sW2[Hh * Hh];     // 4KB
    int tid = threadIdx.x;
    sW2[tid] = W2[tid];
    sW2[tid + 512] = W2[tid + 512];
    int w = tid >> 5, l = tid & 31;
    int dd = w >> 1;                    // 0..7
    int d = blockIdx.x * 8 + dd;
    int b = ((w & 1) << 3) + (l >> 2);  // batch 0..15
    int ho = l & 3;                     // h-oct 0..3 (halves 8ho..8ho+7)
    __syncthreads();
    int start = __ldg(&g_ptr[d]), end = __ldg(&g_ptr[d + 1]);
    const uint4* yb = (const uint4*)g_y1h + b * 4 + ho;  // lane-constant
    float4 aA = {0,0,0,0}, aB = {0,0,0,0};
    int e = start;
    for (; e + 3 < end; e += 4) {
        int o0 = __ldg(&g_csr_src[e]);
        int o1 = __ldg(&g_csr_src[e + 1]);
        int o2 = __ldg(&g_csr_src[e + 2]);
        int o3 = __ldg(&g_csr_src[e + 3]);
        uint4 v0 = __ldg(yb + o0);
        uint4 v1 = __ldg(yb + o1);
        uint4 v2 = __ldg(yb + o2);
        uint4 v3 = __ldg(yb + o3);
#pragma unroll
        for (int k = 0; k < 4; k++) {
            uint4 v = (k == 0) ? v0 : (k == 1) ? v1 : (k == 2) ? v2 : v3;
            float2 f0 = h2f2(v.x), f1 = h2f2(v.y), f2 = h2f2(v.z), f3 = h2f2(v.w);
            aA.x += f0.x; aA.y += f0.y; aA.z += f1.x; aA.w += f1.y;
            aB.x += f2.x; aB.y += f2.y; aB.z += f3.x; aB.w += f3.y;
        }
    }
    for (; e < end; e++) {
        uint4 v = __ldg(yb + __ldg(&g_csr_src[e]));
        float2 f0 = h2f2(v.x), f1 = h2f2(v.y), f2 = h2f2(v.z), f3 = h2f2(v.w);
        aA.x += f0.x; aA.y += f0.y; aA.z += f1.x; aA.w += f1.y;
        aB.x += f2.x; aB.y += f2.y; aB.z += f3.x; aB.w += f3.y;
    }
    float di = g_dinv[d];
    float4 biasA = __ldg(&((const float4*)b1)[2 * ho]);
    float4 biasB = __ldg(&((const float4*)b1)[2 * ho + 1]);
    float4 hvA, hvB;
    hvA.x = fmaxf(di * aA.x + biasA.x, 0.f);
    hvA.y = fmaxf(di * aA.y + biasA.y, 0.f);
    hvA.z = fmaxf(di * aA.z + biasA.z, 0.f);
    hvA.w = fmaxf(di * aA.w + biasA.w, 0.f);
    hvB.x = fmaxf(di * aB.x + biasB.x, 0.f);
    hvB.y = fmaxf(di * aB.y + biasB.y, 0.f);
    hvB.z = fmaxf(di * aB.z + biasB.z, 0.f);
    hvB.w = fmaxf(di * aB.w + biasB.w, 0.f);
    // W2 multiply: out[h] = sum_h' hv[h'] * W2[h'][h]; h' spread over 4-lane grp
    float4 outA = {0,0,0,0}, outB = {0,0,0,0};
    int srcbase = l & 28;               // start lane of my (batch) group
#pragma unroll
    for (int q = 0; q < 4; q++) {
        int sl = srcbase + q;
        float va[8];
        va[0] = __shfl_sync(0xffffffffu, hvA.x, sl);
        va[1] = __shfl_sync(0xffffffffu, hvA.y, sl);
        va[2] = __shfl_sync(0xffffffffu, hvA.z, sl);
        va[3] = __shfl_sync(0xffffffffu, hvA.w, sl);
        va[4] = __shfl_sync(0xffffffffu, hvB.x, sl);
        va[5] = __shfl_sync(0xffffffffu, hvB.y, sl);
        va[6] = __shfl_sync(0xffffffffu, hvB.z, sl);
        va[7] = __shfl_sync(0xffffffffu, hvB.w, sl);
#pragma unroll
        for (int r = 0; r < 8; r++) {
            int hp = 8 * q + r;
            float4 w0 = ((const float4*)&sW2[hp * Hh])[2 * ho];
            float4 w1 = ((const float4*)&sW2[hp * Hh])[2 * ho + 1];
            outA.x += va[r] * w0.x; outA.y += va[r] * w0.y;
            outA.z += va[r] * w0.z; outA.w += va[r] * w0.w;
            outB.x += va[r] * w1.x; outB.y += va[r] * w1.y;
            outB.z += va[r] * w1.z; outB.w += va[r] * w1.w;
        }
    }
    uint4 ob;
    ob.x = h2bits(di * outA.x, di * outA.y);
    ob.y = h2bits(di * outA.z, di * outA.w);
    ob.z = h2bits(di * outB.x, di * outB.y);
    ob.w = h2bits(di * outB.z, di * outB.w);
    // layout [n][b][h]: uint4 index = d*64 + b*4 + ho
    ((uint4*)g_y2h)[(size_t)d * 64 + b * 4 + ho] = ob;
}

// ------------------- 6. layer2 aggregate + relu -> flatT (fp32) -------------
__global__ void __launch_bounds__(512) k_agg2(const float* __restrict__ b2) {
    __shared__ float sT[8][Hh][17];    // 17.4 KB
    int tid = threadIdx.x;
    int w = tid >> 5, l = tid & 31;
    int dd = w >> 1;
    int d = blockIdx.x * 8 + dd;
    int b = ((w & 1) << 3) + (l >> 2);
    int ho = l & 3;
    int start = __ldg(&g_ptr[d]), end = __ldg(&g_ptr[d + 1]);
    const uint4* yb = (const uint4*)g_y2h + b * 4 + ho;
    float4 aA = {0,0,0,0}, aB = {0,0,0,0};
    int e = start;
    for (; e + 3 < end; e += 4) {
        int o0 = __ldg(&g_csr_src[e]);
        int o1 = __ldg(&g_csr_src[e + 1]);
        int o2 = __ldg(&g_csr_src[e + 2]);
        int o3 = __ldg(&g_csr_src[e + 3]);
        uint4 v0 = __ldg(yb + o0);
        uint4 v1 = __ldg(yb + o1);
        uint4 v2 = __ldg(yb + o2);
        uint4 v3 = __ldg(yb + o3);
#pragma unroll
        for (int k = 0; k < 4; k++) {
            uint4 v = (k == 0) ? v0 : (k == 1) ? v1 : (k == 2) ? v2 : v3;
            float2 f0 = h2f2(v.x), f1 = h2f2(v.y), f2 = h2f2(v.z), f3 = h2f2(v.w);
            aA.x += f0.x; aA.y += f0.y; aA.z += f1.x; aA.w += f1.y;
            aB.x += f2.x; aB.y += f2.y; aB.z += f3.x; aB.w += f3.y;
        }
    }
    for (; e < end; e++) {
        uint4 v = __ldg(yb + __ldg(&g_csr_src[e]));
        float2 f0 = h2f2(v.x), f1 = h2f2(v.y), f2 = h2f2(v.z), f3 = h2f2(v.w);
        aA.x += f0.x; aA.y += f0.y; aA.z += f1.x; aA.w += f1.y;
        aB.x += f2.x; aB.y += f2.y; aB.z += f3.x; aB.w += f3.y;
    }
    float di = g_dinv[d];
    float4 biasA = __ldg(&((const float4*)b2)[2 * ho]);
    float4 biasB = __ldg(&((const float4*)b2)[2 * ho + 1]);
    sT[dd][8 * ho + 0][b] = fmaxf(di * aA.x + biasA.x, 0.f);
    sT[dd][8 * ho + 1][b] = fmaxf(di * aA.y + biasA.y, 0.f);
    sT[dd][8 * ho + 2][b] = fmaxf(di * aA.z + biasA.z, 0.f);
    sT[dd][8 * ho + 3][b] = fmaxf(di * aA.w + biasA.w, 0.f);
    sT[dd][8 * ho + 4][b] = fmaxf(di * aB.x + biasB.x, 0.f);
    sT[dd][8 * ho + 5][b] = fmaxf(di * aB.y + biasB.y, 0.f);
    sT[dd][8 * ho + 6][b] = fmaxf(di * aB.z + biasB.z, 0.f);
    sT[dd][8 * ho + 7][b] = fmaxf(di * aB.w + biasB.w, 0.f);
    __syncthreads();
    // write 4096 floats: flatT[(blockIdx*8+ddd)*512 + h*16 + b]
    size_t outbase = (size_t)blockIdx.x * 4096;
#pragma unroll
    for (int i = 0; i < 8; i++) {
        int idx = i * 512 + tid;
        int ddd = idx >> 9, j = idx & 511;
        g_flatT[outbase + idx] = sT[ddd][j >> 4][j & 15];
    }
}

// ------------------- 7. big GEMM: partial[split] = flatT^T chunk @ Wp1 -------
#define GEMM_COMPUTE(BUF, KBASE)                                             \
    {                                                                        \
        _Pragma("unroll")                                                    \
        for (int i = 0; i < 8; i++) {                                        \
            ull wa = pack2(BUF[i].x);                                        \
            ull wb = pack2(BUF[i].y);                                        \
            const ulonglong2* f2 = &sF[((KBASE) + i) * 4];                   \
            _Pragma("unroll")                                                \
            for (int q = 0; q < 4; q++) {                                    \
                ulonglong2 fv = f2[q];                                       \
                acc0[2 * q]     = ffma2(fv.x, wa, acc0[2 * q]);              \
                acc0[2 * q + 1] = ffma2(fv.y, wa, acc0[2 * q + 1]);          \
                acc1[2 * q]     = ffma2(fv.x, wb, acc1[2 * q]);              \
                acc1[2 * q + 1] = ffma2(fv.y, wb, acc1[2 * q + 1]);          \
            }                                                                \
        }                                                                    \
    }

__global__ void __launch_bounds__(256, 2) k_gemm1(const float* __restrict__ Wp1) {
    __shared__ __align__(16) ulonglong2 sF[KLEN * 4];  // 34816 B
    int t = threadIdx.x, sp = blockIdx.x;
    int ks = sp * KLEN;
    int klen = NH - ks;
    if (klen > KLEN) klen = KLEN;          // klen in {544, 64}; nb even
    const ulonglong2* fp = (const ulonglong2*)(g_flatT + (size_t)ks * 16);
    for (int i = t; i < klen * 4; i += 256) sF[i] = __ldg(&fp[i]);
    __syncthreads();

    const float2* wp = (const float2*)Wp1 + (size_t)ks * 256 + t;
    ull acc0[8], acc1[8];
#pragma unroll
    for (int p = 0; p < 8; p++) { acc0[p] = 0ull; acc1[p] = 0ull; }

    int nb = klen >> 3;                    // even (68 or 8)
    float2 A[8], B[8];
#pragma unroll
    for (int i = 0; i < 8; i++) A[i] = __ldg(wp + i * 256);
    for (int bi = 0; bi < nb; bi += 2) {
        const float2* wq = wp + (size_t)(bi + 1) * 2048;
#pragma unroll
        for (int i = 0; i < 8; i++) B[i] = __ldg(wq + i * 256);
        GEMM_COMPUTE(A, bi * 8)
        if (bi + 2 < nb) {
            const float2* wr2 = wp + (size_t)(bi + 2) * 2048;
#pragma unroll
            for (int i = 0; i < 8; i++) A[i] = __ldg(wr2 + i * 256);
        }
        GEMM_COMPUTE(B, (bi + 1) * 8)
    }
    // store partials: layout [sp][j][b] with j0 = 2t
    ull* po = (ull*)g_partial;
    size_t base = (size_t)sp * 4096 + (size_t)(2 * t) * 8;
#pragma unroll
    for (int p = 0; p < 8; p++) {
        po[base + p] = acc0[p];
        po[base + 8 + p] = acc1[p];
    }
}

// ------------------- 8. reduce partials + bias + relu + out-partial ----------
__global__ void __launch_bounds__(256) k_reduce(const float* __restrict__ bp1,
                                                const float* __restrict__ Wp2) {
    __shared__ float sh[256];
    int tid = threadIdx.x;
    int idx = blockIdx.x * 256 + tid;           // [j][b]
    float s = 0.f;
#pragma unroll 8
    for (int sp = 0; sp < SPLITS; sp++) s += g_partial[(size_t)sp * 8192 + idx];
    sh[tid] = fmaxf(s + __ldg(&bp1[idx >> 4]), 0.f);
    __syncthreads();
    // out partial: thread = (b = tid>>4, a = tid&15)
    int b = tid >> 4, a = tid & 15;
    int jbase = blockIdx.x * 16;
    float acc = 0.f;
#pragma unroll
    for (int jl = 0; jl < 16; jl++)
        acc += sh[jl * 16 + b] * __ldg(&Wp2[(jbase + jl) * 16 + a]);
    g_opart[blockIdx.x * 256 + tid] = acc;
}

// ------------------- 9. final: sum 32 out-partials + bias -------------------
__global__ void __launch_bounds__(256) k_outB(const float* __restrict__ bp2,
                                              float* __restrict__ out) {
    int tid = threadIdx.x;
    float acc = 0.f;
#pragma unroll
    for (int k = 0; k < 32; k++) acc += g_opart[k * 256 + tid];
    out[tid] = acc + __ldg(&bp2[tid & 15]);
}

// ----------------------------- launcher -------------------------------------
extern "C" void kernel_launch(void* const* d_in, const int* in_sizes, int n_in,
                              void* d_out, int out_size) {
    const float* features = (const float*)d_in[0];
    const void*  edge_ix  = d_in[1];
    const float* W1  = (const float*)d_in[2];
    const float* b1  = (const float*)d_in[3];
    const float* W2  = (const float*)d_in[4];
    const float* b2  = (const float*)d_in[5];
    const float* Wp1 = (const float*)d_in[6];
    const float* bp1 = (const float*)d_in[7];
    const float* Wp2 = (const float*)d_in[8];
    const float* bp2 = (const float*)d_in[9];
    float* out = (float*)d_out;

    k_init<<<21, 256>>>(edge_ix);
    k_degree<<<DEG_BLOCKS, 1024>>>(edge_ix);
    k_scan<<<1, 1024>>>();
    k_bucket<<<BUCKET_BLOCKS, 256>>>(edge_ix);
    k_xw1<<<XW1_BLOCKS, 256>>>(features, W1);
    k_agg1<<<Nn / 8, 512>>>(W2, b1);
    k_agg2<<<Nn / 8, 512>>>(b2);
    k_gemm1<<<SPLITS, 256>>>(Wp1);
    k_reduce<<<Jj * Bz / 256, 256>>>(bp1, Wp2);
    k_outB<<<1, 256>>>(bp2, out);
}